// round 10
// baseline (speedup 1.0000x reference)
#include <cuda_runtime.h>
#include <math.h>

#define NPAD 1280
#define MAXT 32768
#define NB   128
#define NTHR 256

// ---------------- device scratch (static: allocation at module load, allowed) ----
__device__ float g_px[(size_t)MAXT * NPAD];   // precomputed x-projections (+bias)
__device__ float g_wpack[1024 * NPAD];        // packed x-part weights
__device__ float g_bias[NPAD];
__device__ float g_hbuf[512];
__device__ float g_cbuf[512];
__device__ float g_uwp[128];
__device__ float g_urp[128];
__device__ float g_gates[2];                  // [0]=gw, [1]=go
__device__ unsigned g_bar_count;
__device__ volatile unsigned g_bar_gen;

// ---------------- init (reset barrier state every launch / graph replay) --------
__global__ void init_kernel() {
    g_bar_count = 0u;
    g_bar_gen = 0u;
}

// ---------------- pack x-part weights + biases into one matrix ------------------
// columns: [0,512) Wc_x | [512,1024) Wxh | [1024,1124) Wwp_x | [1124,1224) Wrp_x
//          | 1224 wwg_x | 1225 wrg_x | rest 0
__global__ void pack_kernel(const float* __restrict__ Wc, const float* __restrict__ Wxh,
                            const float* __restrict__ Wwp, const float* __restrict__ Wrp,
                            const float* __restrict__ Wwg, const float* __restrict__ Wrg,
                            const float* __restrict__ bc, const float* __restrict__ bh,
                            const float* __restrict__ bwp, const float* __restrict__ brp,
                            const float* __restrict__ bwg, const float* __restrict__ brg) {
    int stride = gridDim.x * blockDim.x;
    int tid0 = blockIdx.x * blockDim.x + threadIdx.x;
    for (int idx = tid0; idx < 1024 * NPAD; idx += stride) {
        int row = idx / NPAD;
        int col = idx - row * NPAD;
        float v = 0.f;
        if (col < 512)        v = Wc[row * 512 + col];
        else if (col < 1024)  v = Wxh[row * 512 + (col - 512)];
        else if (col < 1124)  v = Wwp[row * 100 + (col - 1024)];
        else if (col < 1224)  v = Wrp[row * 100 + (col - 1124)];
        else if (col == 1224) v = Wwg[row];
        else if (col == 1225) v = Wrg[row];
        g_wpack[idx] = v;
    }
    if (tid0 < NPAD) {
        int t = tid0;
        float b = 0.f;
        if (t < 512)        b = bc[t];
        else if (t < 1024)  b = bh[t - 512];
        else if (t < 1124)  b = bwp[t - 1024];
        else if (t < 1224)  b = brp[t - 1124];
        else if (t == 1224) b = bwg[0];
        else if (t == 1225) b = brg[0];
        g_bias[t] = b;
    }
}

// ---------------- fp32 tiled GEMM: g_px[n,1280] = X[n,1024] @ g_wpack + bias -----
__global__ void __launch_bounds__(256) gemm_kernel(const float* __restrict__ X, int n) {
    __shared__ float As[16][64];       // [k][m]
    __shared__ float Bs[16][64];       // [k][n]
    const int tid = threadIdx.x;
    const int tx = tid & 15;           // N micro
    const int ty = tid >> 4;           // M micro
    const int m0 = blockIdx.x * 64;
    const int n0 = blockIdx.y * 64;

    const int am = tid >> 2;           // row 0..63 within A tile
    const int ak = (tid & 3) * 4;      // k offset 0..12
    const int bk = tid >> 4;           // k row 0..15
    const int bn = (tid & 15) * 4;     // n offset

    float acc[4][4];
#pragma unroll
    for (int i = 0; i < 4; i++)
#pragma unroll
        for (int j = 0; j < 4; j++) acc[i][j] = 0.f;

    for (int kt = 0; kt < 1024; kt += 16) {
        float4 xa;
        if (m0 + am < n)
            xa = *reinterpret_cast<const float4*>(X + (size_t)(m0 + am) * 1024 + kt + ak);
        else
            xa = make_float4(0.f, 0.f, 0.f, 0.f);
        As[ak + 0][am] = xa.x;
        As[ak + 1][am] = xa.y;
        As[ak + 2][am] = xa.z;
        As[ak + 3][am] = xa.w;
        float4 wb = *reinterpret_cast<const float4*>(g_wpack + (size_t)(kt + bk) * NPAD + n0 + bn);
        Bs[bk][bn + 0] = wb.x;
        Bs[bk][bn + 1] = wb.y;
        Bs[bk][bn + 2] = wb.z;
        Bs[bk][bn + 3] = wb.w;
        __syncthreads();
#pragma unroll
        for (int k = 0; k < 16; k++) {
            float4 av = *reinterpret_cast<const float4*>(&As[k][ty * 4]);
            float4 bv = *reinterpret_cast<const float4*>(&Bs[k][tx * 4]);
            float a[4] = {av.x, av.y, av.z, av.w};
            float b[4] = {bv.x, bv.y, bv.z, bv.w};
#pragma unroll
            for (int i = 0; i < 4; i++)
#pragma unroll
                for (int j = 0; j < 4; j++) acc[i][j] += a[i] * b[j];
        }
        __syncthreads();
    }
#pragma unroll
    for (int i = 0; i < 4; i++) {
        int r = m0 + ty * 4 + i;
        if (r >= n) continue;
#pragma unroll
        for (int j = 0; j < 4; j++) {
            int c = n0 + tx * 4 + j;
            g_px[(size_t)r * NPAD + c] = acc[i][j] + g_bias[c];
        }
    }
}

// ---------------- global barrier (all NB CTAs co-resident: NB <= 148) -----------
__device__ __forceinline__ void grid_barrier() {
    __syncthreads();
    if (threadIdx.x == 0) {
        __threadfence();                       // release my CTA's writes (gpu scope)
        unsigned gen = g_bar_gen;
        unsigned rank = atomicAdd(&g_bar_count, 1u);
        if (rank == NB - 1u) {
            atomicExch(&g_bar_count, 0u);
            __threadfence();
            g_bar_gen = gen + 1u;
        } else {
            while (g_bar_gen == gen) { }
        }
        __threadfence();                       // acquire
    }
    __syncthreads();
}

// warp-wide softmax over 100 elements: dst[m] = softmax(ubuf[m] + pxp[m])
__device__ __forceinline__ void warp_softmax(const float* ubuf, const float* __restrict__ pxp,
                                             float* dst) {
    int lane = threadIdx.x & 31;
    float v[4];
#pragma unroll
    for (int q = 0; q < 4; q++) {
        int m = lane + 32 * q;
        v[q] = (m < 100) ? (__ldcg(&ubuf[m]) + __ldg(&pxp[m])) : -1e30f;
    }
    float mx = fmaxf(fmaxf(v[0], v[1]), fmaxf(v[2], v[3]));
#pragma unroll
    for (int off = 16; off > 0; off >>= 1)
        mx = fmaxf(mx, __shfl_xor_sync(0xffffffffu, mx, off));
    float e[4], s = 0.f;
#pragma unroll
    for (int q = 0; q < 4; q++) {
        int m = lane + 32 * q;
        e[q] = (m < 100) ? expf(v[q] - mx) : 0.f;
        s += e[q];
    }
#pragma unroll
    for (int off = 16; off > 0; off >>= 1)
        s += __shfl_xor_sync(0xffffffffu, s, off);
    float inv = 1.f / s;
#pragma unroll
    for (int q = 0; q < 4; q++) {
        int m = lane + 32 * q;
        if (m < 100) dst[m] = e[q] * inv;
    }
}

// ---------------- persistent serial scan kernel ---------------------------------
// CTA b owns output columns j0=4b..4b+3 of Wc_h/Whh/Wrh and memW, plus (b<100)
// column b of Wwp_h/Wrp_h; CTA 0 owns the two gate dots.
// Group g = tid/16 (16 lanes each):
//   g 0..3  : u_c  = h . Wc_h[:,j0+g]
//   g 4..7  : u_hh = h . Whh[:,j0+g-4]
//   g 8     : u_wp = h . Wwp_h[:,b]            (b<100)
//   g 9     : u_rp = h . Wrp_h[:,b]            (b<100)
//   g 10,11 : gate dots (b==0)
//   g 12..15: cW   = c . Wrh[:,j0+g-12]        (phase B)
__global__ void __launch_bounds__(NTHR) serial_kernel(
    const float* __restrict__ Wc, const float* __restrict__ Wwp, const float* __restrict__ Wrp,
    const float* __restrict__ Wwg, const float* __restrict__ Wrg,
    const float* __restrict__ Whh, const float* __restrict__ Wrh,
    float* __restrict__ out, int n) {
    const int b = blockIdx.x;
    const int tid = threadIdx.x;
    const int g = tid >> 4;
    const int l = tid & 15;
    const int j0 = b * 4;

    __shared__ float sh[512];
    __shared__ float sc[512];
    __shared__ float s_ar[100];
    __shared__ float s_awprev[100];
    __shared__ float s_u[16];
    __shared__ float s_cw[4];
    __shared__ float s_go, s_gwprev;
    __shared__ float s_memW[400];     // [cc*100 + row]

    // select this thread's dot column source
    const float* src = Wc;            // dummy
    int stride = 512;
    bool active = true;
    if (g < 4)        { src = Wc  + 1024 * 512 + (j0 + g);       stride = 512; }
    else if (g < 8)   { src = Whh + (j0 + g - 4);                stride = 512; }
    else if (g == 8)  { active = (b < 100); if (active) { src = Wwp + 1024 * 100 + b; stride = 100; } }
    else if (g == 9)  { active = (b < 100); if (active) { src = Wrp + 1024 * 100 + b; stride = 100; } }
    else if (g == 10) { active = (b == 0);  if (active) { src = Wwg + 1024; stride = 1; } }
    else if (g == 11) { active = (b == 0);  if (active) { src = Wrg + 1024; stride = 1; } }
    else              { src = Wrh + (j0 + g - 12);               stride = 512; }

    // weights resident in registers for the whole scan
    float w[32];
#pragma unroll
    for (int k = 0; k < 32; k++) w[k] = 0.f;
    if (active) {
#pragma unroll
        for (int k = 0; k < 32; k++) w[k] = __ldg(src + (size_t)(l + 16 * k) * stride);
    }
    for (int i = tid; i < 400; i += NTHR) s_memW[i] = 0.f;

    for (int t = 0; t < n; t++) {
        const float* pxr = g_px + (size_t)t * NPAD;
        // -------- Phase A --------
        for (int i = tid; i < 512; i += NTHR)
            sh[i] = (t == 0) ? 0.f : __ldcg(&g_hbuf[i]);
        if (t > 0) {
            float gwp = s_gwprev;
            for (int i = tid; i < 400; i += NTHR) {
                int cc = i / 100;
                int row = i - cc * 100;
                float a = s_awprev[row];
                s_memW[i] = gwp * a * s_cw[cc] + (1.f - a) * s_memW[i];
            }
        }
        __syncthreads();
        if (g < 12 && active) {
            float acc = 0.f;
#pragma unroll
            for (int k = 0; k < 32; k++) acc += w[k] * sh[l + 16 * k];
            acc += __shfl_down_sync(0xffffffffu, acc, 8, 16);
            acc += __shfl_down_sync(0xffffffffu, acc, 4, 16);
            acc += __shfl_down_sync(0xffffffffu, acc, 2, 16);
            acc += __shfl_down_sync(0xffffffffu, acc, 1, 16);
            if (l == 0) s_u[g] = acc;
        }
        __syncthreads();
        if (tid < 4) {
            float c = __ldg(&pxr[j0 + tid]) + s_u[tid];
            g_cbuf[j0 + tid] = fmaxf(c, 0.f);
        }
        if (b < 100) {
            if (tid == 4) g_uwp[b] = s_u[8];
            if (tid == 5) g_urp[b] = s_u[9];
        }
        if (b == 0) {
            if (tid == 6) g_gates[0] = 1.f / (1.f + expf(-(__ldg(&pxr[1224]) + s_u[10])));
            if (tid == 7) g_gates[1] = 1.f / (1.f + expf(-(__ldg(&pxr[1225]) + s_u[11])));
        }
        grid_barrier();
        // -------- Phase B --------
        for (int i = tid; i < 512; i += NTHR) sc[i] = __ldcg(&g_cbuf[i]);
        int wid = tid >> 5;
        if (wid == 0) {
            warp_softmax(g_urp, pxr + 1124, s_ar);
        } else if (wid == 1) {
            warp_softmax(g_uwp, pxr + 1024, s_awprev);
            if ((tid & 31) == 0) {
                s_gwprev = __ldcg(&g_gates[0]);
                s_go     = __ldcg(&g_gates[1]);
            }
        }
        __syncthreads();
        if (g >= 12) {
            float acc = 0.f;
#pragma unroll
            for (int k = 0; k < 32; k++) acc += w[k] * sc[l + 16 * k];
            acc += __shfl_down_sync(0xffffffffu, acc, 8, 16);
            acc += __shfl_down_sync(0xffffffffu, acc, 4, 16);
            acc += __shfl_down_sync(0xffffffffu, acc, 2, 16);
            acc += __shfl_down_sync(0xffffffffu, acc, 1, 16);
            if (l == 0) s_cw[g - 12] = acc;
        }
        if (g < 4) {
            float acc = 0.f;
            for (int row = l; row < 100; row += 16)
                acc += s_ar[row] * s_memW[g * 100 + row];
            acc += __shfl_down_sync(0xffffffffu, acc, 8, 16);
            acc += __shfl_down_sync(0xffffffffu, acc, 4, 16);
            acc += __shfl_down_sync(0xffffffffu, acc, 2, 16);
            acc += __shfl_down_sync(0xffffffffu, acc, 1, 16);
            if (l == 0) {
                float hn = __ldg(&pxr[512 + j0 + g]) + s_u[4 + g] + s_go * acc;
                hn = fmaxf(hn, 0.f);
                out[(size_t)t * 512 + j0 + g] = hn;
                g_hbuf[j0 + g] = hn;
            }
        }
        grid_barrier();
    }
}

// ---------------- launch --------------------------------------------------------
extern "C" void kernel_launch(void* const* d_in, const int* in_sizes, int n_in,
                              void* d_out, int out_size) {
    const float* X   = (const float*)d_in[0];
    const float* Wc  = (const float*)d_in[1];
    const float* bc  = (const float*)d_in[2];
    const float* Wwg = (const float*)d_in[3];
    const float* bwg = (const float*)d_in[4];
    const float* Wwp = (const float*)d_in[5];
    const float* bwp = (const float*)d_in[6];
    const float* Wrg = (const float*)d_in[7];
    const float* brg = (const float*)d_in[8];
    const float* Wrp = (const float*)d_in[9];
    const float* brp = (const float*)d_in[10];
    const float* Wxh = (const float*)d_in[11];
    const float* Wrh = (const float*)d_in[12];
    const float* Whh = (const float*)d_in[13];
    const float* bh  = (const float*)d_in[14];
    float* out = (float*)d_out;

    int n = in_sizes[0] / 1024;
    if (n > MAXT) n = MAXT;

    init_kernel<<<1, 1>>>();
    pack_kernel<<<256, 256>>>(Wc, Wxh, Wwp, Wrp, Wwg, Wrg, bc, bh, bwp, brp, bwg, brg);
    dim3 gg((n + 63) / 64, NPAD / 64);
    gemm_kernel<<<gg, 256>>>(X, n);
    serial_kernel<<<NB, NTHR>>>(Wc, Wwp, Wrp, Wwg, Wrg, Whh, Wrh, out, n);
}

// round 11
// speedup vs baseline: 1.0004x; 1.0004x over previous
#include <cuda_runtime.h>
#include <math.h>

#define NPAD 1280
#define MAXT 32768
#define NB   128
#define NTHR 256

// ---------------- device scratch (static: allocation at module load, allowed) ----
__device__ float g_px[(size_t)MAXT * NPAD];   // precomputed x-projections (+bias)
__device__ float g_wpack[1024 * NPAD];        // packed x-part weights
__device__ float g_bias[NPAD];
__device__ float g_hbuf[512];
__device__ float g_cbuf[512];
__device__ float g_uwp[128];
__device__ float g_urp[128];
__device__ float g_gates[2];                  // [0]=gw, [1]=go
__device__ unsigned g_bar_count;
__device__ volatile unsigned g_bar_gen;

// ---------------- init (reset barrier state every launch / graph replay) --------
__global__ void init_kernel() {
    g_bar_count = 0u;
    g_bar_gen = 0u;
}

// ---------------- pack x-part weights + biases into one matrix ------------------
// columns: [0,512) Wc_x | [512,1024) Wxh | [1024,1124) Wwp_x | [1124,1224) Wrp_x
//          | 1224 wwg_x | 1225 wrg_x | rest 0
__global__ void pack_kernel(const float* __restrict__ Wc, const float* __restrict__ Wxh,
                            const float* __restrict__ Wwp, const float* __restrict__ Wrp,
                            const float* __restrict__ Wwg, const float* __restrict__ Wrg,
                            const float* __restrict__ bc, const float* __restrict__ bh,
                            const float* __restrict__ bwp, const float* __restrict__ brp,
                            const float* __restrict__ bwg, const float* __restrict__ brg) {
    int stride = gridDim.x * blockDim.x;
    int tid0 = blockIdx.x * blockDim.x + threadIdx.x;
    for (int idx = tid0; idx < 1024 * NPAD; idx += stride) {
        int row = idx / NPAD;
        int col = idx - row * NPAD;
        float v = 0.f;
        if (col < 512)        v = Wc[row * 512 + col];
        else if (col < 1024)  v = Wxh[row * 512 + (col - 512)];
        else if (col < 1124)  v = Wwp[row * 100 + (col - 1024)];
        else if (col < 1224)  v = Wrp[row * 100 + (col - 1124)];
        else if (col == 1224) v = Wwg[row];
        else if (col == 1225) v = Wrg[row];
        g_wpack[idx] = v;
    }
    if (tid0 < NPAD) {
        int t = tid0;
        float b = 0.f;
        if (t < 512)        b = bc[t];
        else if (t < 1024)  b = bh[t - 512];
        else if (t < 1124)  b = bwp[t - 1024];
        else if (t < 1224)  b = brp[t - 1124];
        else if (t == 1224) b = bwg[0];
        else if (t == 1225) b = brg[0];
        g_bias[t] = b;
    }
}

// ---------------- fp32 tiled GEMM: g_px[n,1280] = X[n,1024] @ g_wpack + bias -----
__global__ void __launch_bounds__(256) gemm_kernel(const float* __restrict__ X, int n) {
    __shared__ float As[16][64];       // [k][m]
    __shared__ float Bs[16][64];       // [k][n]
    const int tid = threadIdx.x;
    const int tx = tid & 15;           // N micro
    const int ty = tid >> 4;           // M micro
    const int m0 = blockIdx.x * 64;
    const int n0 = blockIdx.y * 64;

    const int am = tid >> 2;           // row 0..63 within A tile
    const int ak = (tid & 3) * 4;      // k offset 0..12
    const int bk = tid >> 4;           // k row 0..15
    const int bn = (tid & 15) * 4;     // n offset

    float acc[4][4];
#pragma unroll
    for (int i = 0; i < 4; i++)
#pragma unroll
        for (int j = 0; j < 4; j++) acc[i][j] = 0.f;

    for (int kt = 0; kt < 1024; kt += 16) {
        float4 xa;
        if (m0 + am < n)
            xa = *reinterpret_cast<const float4*>(X + (size_t)(m0 + am) * 1024 + kt + ak);
        else
            xa = make_float4(0.f, 0.f, 0.f, 0.f);
        As[ak + 0][am] = xa.x;
        As[ak + 1][am] = xa.y;
        As[ak + 2][am] = xa.z;
        As[ak + 3][am] = xa.w;
        float4 wb = *reinterpret_cast<const float4*>(g_wpack + (size_t)(kt + bk) * NPAD + n0 + bn);
        Bs[bk][bn + 0] = wb.x;
        Bs[bk][bn + 1] = wb.y;
        Bs[bk][bn + 2] = wb.z;
        Bs[bk][bn + 3] = wb.w;
        __syncthreads();
#pragma unroll
        for (int k = 0; k < 16; k++) {
            float4 av = *reinterpret_cast<const float4*>(&As[k][ty * 4]);
            float4 bv = *reinterpret_cast<const float4*>(&Bs[k][tx * 4]);
            float a[4] = {av.x, av.y, av.z, av.w};
            float b[4] = {bv.x, bv.y, bv.z, bv.w};
#pragma unroll
            for (int i = 0; i < 4; i++)
#pragma unroll
                for (int j = 0; j < 4; j++) acc[i][j] += a[i] * b[j];
        }
        __syncthreads();
    }
#pragma unroll
    for (int i = 0; i < 4; i++) {
        int r = m0 + ty * 4 + i;
        if (r >= n) continue;
#pragma unroll
        for (int j = 0; j < 4; j++) {
            int c = n0 + tx * 4 + j;
            g_px[(size_t)r * NPAD + c] = acc[i][j] + g_bias[c];
        }
    }
}

// ---------------- global barrier (all NB CTAs co-resident: NB <= 148) -----------
__device__ __forceinline__ void grid_barrier() {
    __syncthreads();
    if (threadIdx.x == 0) {
        __threadfence();                       // release my CTA's writes (gpu scope)
        unsigned gen = g_bar_gen;
        unsigned rank = atomicAdd(&g_bar_count, 1u);
        if (rank == NB - 1u) {
            atomicExch(&g_bar_count, 0u);
            __threadfence();
            g_bar_gen = gen + 1u;
        } else {
            while (g_bar_gen == gen) { }
        }
        __threadfence();                       // acquire
    }
    __syncthreads();
}

// warp-wide softmax over 100 elements: dst[m] = softmax(ubuf[m] + pxp[m])
__device__ __forceinline__ void warp_softmax(const float* ubuf, const float* __restrict__ pxp,
                                             float* dst) {
    int lane = threadIdx.x & 31;
    float v[4];
#pragma unroll
    for (int q = 0; q < 4; q++) {
        int m = lane + 32 * q;
        v[q] = (m < 100) ? (__ldcg(&ubuf[m]) + __ldg(&pxp[m])) : -1e30f;
    }
    float mx = fmaxf(fmaxf(v[0], v[1]), fmaxf(v[2], v[3]));
#pragma unroll
    for (int off = 16; off > 0; off >>= 1)
        mx = fmaxf(mx, __shfl_xor_sync(0xffffffffu, mx, off));
    float e[4], s = 0.f;
#pragma unroll
    for (int q = 0; q < 4; q++) {
        int m = lane + 32 * q;
        e[q] = (m < 100) ? expf(v[q] - mx) : 0.f;
        s += e[q];
    }
#pragma unroll
    for (int off = 16; off > 0; off >>= 1)
        s += __shfl_xor_sync(0xffffffffu, s, off);
    float inv = 1.f / s;
#pragma unroll
    for (int q = 0; q < 4; q++) {
        int m = lane + 32 * q;
        if (m < 100) dst[m] = e[q] * inv;
    }
}

// ---------------- persistent serial scan kernel ---------------------------------
// CTA b owns output columns j0=4b..4b+3 of Wc_h/Whh/Wrh and memW, plus (b<100)
// column b of Wwp_h/Wrp_h; CTA 0 owns the two gate dots.
// Group g = tid/16 (16 lanes each):
//   g 0..3  : u_c  = h . Wc_h[:,j0+g]
//   g 4..7  : u_hh = h . Whh[:,j0+g-4]
//   g 8     : u_wp = h . Wwp_h[:,b]            (b<100)
//   g 9     : u_rp = h . Wrp_h[:,b]            (b<100)
//   g 10,11 : gate dots (b==0)
//   g 12..15: cW   = c . Wrh[:,j0+g-12]        (phase B)
__global__ void __launch_bounds__(NTHR) serial_kernel(
    const float* __restrict__ Wc, const float* __restrict__ Wwp, const float* __restrict__ Wrp,
    const float* __restrict__ Wwg, const float* __restrict__ Wrg,
    const float* __restrict__ Whh, const float* __restrict__ Wrh,
    float* __restrict__ out, int n) {
    const int b = blockIdx.x;
    const int tid = threadIdx.x;
    const int g = tid >> 4;
    const int l = tid & 15;
    const int j0 = b * 4;

    __shared__ float sh[512];
    __shared__ float sc[512];
    __shared__ float s_ar[100];
    __shared__ float s_awprev[100];
    __shared__ float s_u[16];
    __shared__ float s_cw[4];
    __shared__ float s_go, s_gwprev;
    __shared__ float s_memW[400];     // [cc*100 + row]

    // select this thread's dot column source
    const float* src = Wc;            // dummy
    int stride = 512;
    bool active = true;
    if (g < 4)        { src = Wc  + 1024 * 512 + (j0 + g);       stride = 512; }
    else if (g < 8)   { src = Whh + (j0 + g - 4);                stride = 512; }
    else if (g == 8)  { active = (b < 100); if (active) { src = Wwp + 1024 * 100 + b; stride = 100; } }
    else if (g == 9)  { active = (b < 100); if (active) { src = Wrp + 1024 * 100 + b; stride = 100; } }
    else if (g == 10) { active = (b == 0);  if (active) { src = Wwg + 1024; stride = 1; } }
    else if (g == 11) { active = (b == 0);  if (active) { src = Wrg + 1024; stride = 1; } }
    else              { src = Wrh + (j0 + g - 12);               stride = 512; }

    // weights resident in registers for the whole scan
    float w[32];
#pragma unroll
    for (int k = 0; k < 32; k++) w[k] = 0.f;
    if (active) {
#pragma unroll
        for (int k = 0; k < 32; k++) w[k] = __ldg(src + (size_t)(l + 16 * k) * stride);
    }
    for (int i = tid; i < 400; i += NTHR) s_memW[i] = 0.f;

    for (int t = 0; t < n; t++) {
        const float* pxr = g_px + (size_t)t * NPAD;
        // -------- Phase A --------
        for (int i = tid; i < 512; i += NTHR)
            sh[i] = (t == 0) ? 0.f : __ldcg(&g_hbuf[i]);
        if (t > 0) {
            float gwp = s_gwprev;
            for (int i = tid; i < 400; i += NTHR) {
                int cc = i / 100;
                int row = i - cc * 100;
                float a = s_awprev[row];
                s_memW[i] = gwp * a * s_cw[cc] + (1.f - a) * s_memW[i];
            }
        }
        __syncthreads();
        if (g < 12 && active) {
            float acc = 0.f;
#pragma unroll
            for (int k = 0; k < 32; k++) acc += w[k] * sh[l + 16 * k];
            acc += __shfl_down_sync(0xffffffffu, acc, 8, 16);
            acc += __shfl_down_sync(0xffffffffu, acc, 4, 16);
            acc += __shfl_down_sync(0xffffffffu, acc, 2, 16);
            acc += __shfl_down_sync(0xffffffffu, acc, 1, 16);
            if (l == 0) s_u[g] = acc;
        }
        __syncthreads();
        if (tid < 4) {
            float c = __ldg(&pxr[j0 + tid]) + s_u[tid];
            g_cbuf[j0 + tid] = fmaxf(c, 0.f);
        }
        if (b < 100) {
            if (tid == 4) g_uwp[b] = s_u[8];
            if (tid == 5) g_urp[b] = s_u[9];
        }
        if (b == 0) {
            if (tid == 6) g_gates[0] = 1.f / (1.f + expf(-(__ldg(&pxr[1224]) + s_u[10])));
            if (tid == 7) g_gates[1] = 1.f / (1.f + expf(-(__ldg(&pxr[1225]) + s_u[11])));
        }
        grid_barrier();
        // -------- Phase B --------
        for (int i = tid; i < 512; i += NTHR) sc[i] = __ldcg(&g_cbuf[i]);
        int wid = tid >> 5;
        if (wid == 0) {
            warp_softmax(g_urp, pxr + 1124, s_ar);
        } else if (wid == 1) {
            warp_softmax(g_uwp, pxr + 1024, s_awprev);
            if ((tid & 31) == 0) {
                s_gwprev = __ldcg(&g_gates[0]);
                s_go     = __ldcg(&g_gates[1]);
            }
        }
        __syncthreads();
        if (g >= 12) {
            float acc = 0.f;
#pragma unroll
            for (int k = 0; k < 32; k++) acc += w[k] * sc[l + 16 * k];
            acc += __shfl_down_sync(0xffffffffu, acc, 8, 16);
            acc += __shfl_down_sync(0xffffffffu, acc, 4, 16);
            acc += __shfl_down_sync(0xffffffffu, acc, 2, 16);
            acc += __shfl_down_sync(0xffffffffu, acc, 1, 16);
            if (l == 0) s_cw[g - 12] = acc;
        }
        if (g < 4) {
            float acc = 0.f;
            for (int row = l; row < 100; row += 16)
                acc += s_ar[row] * s_memW[g * 100 + row];
            acc += __shfl_down_sync(0xffffffffu, acc, 8, 16);
            acc += __shfl_down_sync(0xffffffffu, acc, 4, 16);
            acc += __shfl_down_sync(0xffffffffu, acc, 2, 16);
            acc += __shfl_down_sync(0xffffffffu, acc, 1, 16);
            if (l == 0) {
                float hn = __ldg(&pxr[512 + j0 + g]) + s_u[4 + g] + s_go * acc;
                hn = fmaxf(hn, 0.f);
                out[(size_t)t * 512 + j0 + g] = hn;
                g_hbuf[j0 + g] = hn;
            }
        }
        grid_barrier();
    }
}

// ---------------- launch --------------------------------------------------------
extern "C" void kernel_launch(void* const* d_in, const int* in_sizes, int n_in,
                              void* d_out, int out_size) {
    const float* X   = (const float*)d_in[0];
    const float* Wc  = (const float*)d_in[1];
    const float* bc  = (const float*)d_in[2];
    const float* Wwg = (const float*)d_in[3];
    const float* bwg = (const float*)d_in[4];
    const float* Wwp = (const float*)d_in[5];
    const float* bwp = (const float*)d_in[6];
    const float* Wrg = (const float*)d_in[7];
    const float* brg = (const float*)d_in[8];
    const float* Wrp = (const float*)d_in[9];
    const float* brp = (const float*)d_in[10];
    const float* Wxh = (const float*)d_in[11];
    const float* Wrh = (const float*)d_in[12];
    const float* Whh = (const float*)d_in[13];
    const float* bh  = (const float*)d_in[14];
    float* out = (float*)d_out;

    int n = in_sizes[0] / 1024;
    if (n > MAXT) n = MAXT;

    init_kernel<<<1, 1>>>();
    pack_kernel<<<256, 256>>>(Wc, Wxh, Wwp, Wrp, Wwg, Wrg, bc, bh, bwp, brp, bwg, brg);
    dim3 gg((n + 63) / 64, NPAD / 64);
    gemm_kernel<<<gg, 256>>>(X, n);
    serial_kernel<<<NB, NTHR>>>(Wc, Wwp, Wrp, Wwg, Wrg, Whh, Wrh, out, n);
}

// round 12
// speedup vs baseline: 1.0068x; 1.0064x over previous
#include <cuda_runtime.h>
#include <math.h>

#define NPAD 1280
#define MAXT 32768
#define NB   128
#define NTHR 256

// ---------------- device scratch (static: allocation at module load, allowed) ----
__device__ float g_px[(size_t)MAXT * NPAD];   // precomputed x-projections (+bias)
__device__ float g_wpack[1024 * NPAD];        // packed x-part weights
__device__ float g_bias[NPAD];
__device__ float g_hbuf[512];
__device__ float g_cbuf[512];
__device__ float g_uwp[128];
__device__ float g_urp[128];
__device__ float g_gates[2];                  // [0]=gw, [1]=go
__device__ unsigned g_bar_count;
__device__ volatile unsigned g_bar_gen;

// ---------------- init (reset barrier state every launch / graph replay) --------
__global__ void init_kernel() {
    g_bar_count = 0u;
    g_bar_gen = 0u;
}

// ---------------- pack x-part weights + biases into one matrix ------------------
// columns: [0,512) Wc_x | [512,1024) Wxh | [1024,1124) Wwp_x | [1124,1224) Wrp_x
//          | 1224 wwg_x | 1225 wrg_x | rest 0
__global__ void pack_kernel(const float* __restrict__ Wc, const float* __restrict__ Wxh,
                            const float* __restrict__ Wwp, const float* __restrict__ Wrp,
                            const float* __restrict__ Wwg, const float* __restrict__ Wrg,
                            const float* __restrict__ bc, const float* __restrict__ bh,
                            const float* __restrict__ bwp, const float* __restrict__ brp,
                            const float* __restrict__ bwg, const float* __restrict__ brg) {
    int stride = gridDim.x * blockDim.x;
    int tid0 = blockIdx.x * blockDim.x + threadIdx.x;
    for (int idx = tid0; idx < 1024 * NPAD; idx += stride) {
        int row = idx / NPAD;
        int col = idx - row * NPAD;
        float v = 0.f;
        if (col < 512)        v = Wc[row * 512 + col];
        else if (col < 1024)  v = Wxh[row * 512 + (col - 512)];
        else if (col < 1124)  v = Wwp[row * 100 + (col - 1024)];
        else if (col < 1224)  v = Wrp[row * 100 + (col - 1124)];
        else if (col == 1224) v = Wwg[row];
        else if (col == 1225) v = Wrg[row];
        g_wpack[idx] = v;
    }
    if (tid0 < NPAD) {
        int t = tid0;
        float b = 0.f;
        if (t < 512)        b = bc[t];
        else if (t < 1024)  b = bh[t - 512];
        else if (t < 1124)  b = bwp[t - 1024];
        else if (t < 1224)  b = brp[t - 1124];
        else if (t == 1224) b = bwg[0];
        else if (t == 1225) b = brg[0];
        g_bias[t] = b;
    }
}

// ---------------- fp32 tiled GEMM: g_px[n,1280] = X[n,1024] @ g_wpack + bias -----
__global__ void __launch_bounds__(256) gemm_kernel(const float* __restrict__ X, int n) {
    __shared__ float As[16][64];       // [k][m]
    __shared__ float Bs[16][64];       // [k][n]
    const int tid = threadIdx.x;
    const int tx = tid & 15;           // N micro
    const int ty = tid >> 4;           // M micro
    const int m0 = blockIdx.x * 64;
    const int n0 = blockIdx.y * 64;

    const int am = tid >> 2;           // row 0..63 within A tile
    const int ak = (tid & 3) * 4;      // k offset 0..12
    const int bk = tid >> 4;           // k row 0..15
    const int bn = (tid & 15) * 4;     // n offset

    float acc[4][4];
#pragma unroll
    for (int i = 0; i < 4; i++)
#pragma unroll
        for (int j = 0; j < 4; j++) acc[i][j] = 0.f;

    for (int kt = 0; kt < 1024; kt += 16) {
        float4 xa;
        if (m0 + am < n)
            xa = *reinterpret_cast<const float4*>(X + (size_t)(m0 + am) * 1024 + kt + ak);
        else
            xa = make_float4(0.f, 0.f, 0.f, 0.f);
        As[ak + 0][am] = xa.x;
        As[ak + 1][am] = xa.y;
        As[ak + 2][am] = xa.z;
        As[ak + 3][am] = xa.w;
        float4 wb = *reinterpret_cast<const float4*>(g_wpack + (size_t)(kt + bk) * NPAD + n0 + bn);
        Bs[bk][bn + 0] = wb.x;
        Bs[bk][bn + 1] = wb.y;
        Bs[bk][bn + 2] = wb.z;
        Bs[bk][bn + 3] = wb.w;
        __syncthreads();
#pragma unroll
        for (int k = 0; k < 16; k++) {
            float4 av = *reinterpret_cast<const float4*>(&As[k][ty * 4]);
            float4 bv = *reinterpret_cast<const float4*>(&Bs[k][tx * 4]);
            float a[4] = {av.x, av.y, av.z, av.w};
            float b[4] = {bv.x, bv.y, bv.z, bv.w};
#pragma unroll
            for (int i = 0; i < 4; i++)
#pragma unroll
                for (int j = 0; j < 4; j++) acc[i][j] += a[i] * b[j];
        }
        __syncthreads();
    }
#pragma unroll
    for (int i = 0; i < 4; i++) {
        int r = m0 + ty * 4 + i;
        if (r >= n) continue;
#pragma unroll
        for (int j = 0; j < 4; j++) {
            int c = n0 + tx * 4 + j;
            g_px[(size_t)r * NPAD + c] = acc[i][j] + g_bias[c];
        }
    }
}

// ---------------- global barrier (all NB CTAs co-resident: NB <= 148) -----------
__device__ __forceinline__ void grid_barrier() {
    __syncthreads();
    if (threadIdx.x == 0) {
        __threadfence();                       // release my CTA's writes (gpu scope)
        unsigned gen = g_bar_gen;
        unsigned rank = atomicAdd(&g_bar_count, 1u);
        if (rank == NB - 1u) {
            atomicExch(&g_bar_count, 0u);
            __threadfence();
            g_bar_gen = gen + 1u;
        } else {
            while (g_bar_gen == gen) { }
        }
        __threadfence();                       // acquire
    }
    __syncthreads();
}

// warp-wide softmax over 100 elements: dst[m] = softmax(ubuf[m] + pxp[m])
__device__ __forceinline__ void warp_softmax(const float* ubuf, const float* __restrict__ pxp,
                                             float* dst) {
    int lane = threadIdx.x & 31;
    float v[4];
#pragma unroll
    for (int q = 0; q < 4; q++) {
        int m = lane + 32 * q;
        v[q] = (m < 100) ? (__ldcg(&ubuf[m]) + __ldg(&pxp[m])) : -1e30f;
    }
    float mx = fmaxf(fmaxf(v[0], v[1]), fmaxf(v[2], v[3]));
#pragma unroll
    for (int off = 16; off > 0; off >>= 1)
        mx = fmaxf(mx, __shfl_xor_sync(0xffffffffu, mx, off));
    float e[4], s = 0.f;
#pragma unroll
    for (int q = 0; q < 4; q++) {
        int m = lane + 32 * q;
        e[q] = (m < 100) ? expf(v[q] - mx) : 0.f;
        s += e[q];
    }
#pragma unroll
    for (int off = 16; off > 0; off >>= 1)
        s += __shfl_xor_sync(0xffffffffu, s, off);
    float inv = 1.f / s;
#pragma unroll
    for (int q = 0; q < 4; q++) {
        int m = lane + 32 * q;
        if (m < 100) dst[m] = e[q] * inv;
    }
}

// ---------------- persistent serial scan kernel ---------------------------------
// CTA b owns output columns j0=4b..4b+3 of Wc_h/Whh/Wrh and memW, plus (b<100)
// column b of Wwp_h/Wrp_h; CTA 0 owns the two gate dots.
// Group g = tid/16 (16 lanes each):
//   g 0..3  : u_c  = h . Wc_h[:,j0+g]
//   g 4..7  : u_hh = h . Whh[:,j0+g-4]
//   g 8     : u_wp = h . Wwp_h[:,b]            (b<100)
//   g 9     : u_rp = h . Wrp_h[:,b]            (b<100)
//   g 10,11 : gate dots (b==0)
//   g 12..15: cW   = c . Wrh[:,j0+g-12]        (phase B)
__global__ void __launch_bounds__(NTHR) serial_kernel(
    const float* __restrict__ Wc, const float* __restrict__ Wwp, const float* __restrict__ Wrp,
    const float* __restrict__ Wwg, const float* __restrict__ Wrg,
    const float* __restrict__ Whh, const float* __restrict__ Wrh,
    float* __restrict__ out, int n) {
    const int b = blockIdx.x;
    const int tid = threadIdx.x;
    const int g = tid >> 4;
    const int l = tid & 15;
    const int j0 = b * 4;

    __shared__ float sh[512];
    __shared__ float sc[512];
    __shared__ float s_ar[100];
    __shared__ float s_awprev[100];
    __shared__ float s_u[16];
    __shared__ float s_cw[4];
    __shared__ float s_go, s_gwprev;
    __shared__ float s_memW[400];     // [cc*100 + row]

    // select this thread's dot column source
    const float* src = Wc;            // dummy
    int stride = 512;
    bool active = true;
    if (g < 4)        { src = Wc  + 1024 * 512 + (j0 + g);       stride = 512; }
    else if (g < 8)   { src = Whh + (j0 + g - 4);                stride = 512; }
    else if (g == 8)  { active = (b < 100); if (active) { src = Wwp + 1024 * 100 + b; stride = 100; } }
    else if (g == 9)  { active = (b < 100); if (active) { src = Wrp + 1024 * 100 + b; stride = 100; } }
    else if (g == 10) { active = (b == 0);  if (active) { src = Wwg + 1024; stride = 1; } }
    else if (g == 11) { active = (b == 0);  if (active) { src = Wrg + 1024; stride = 1; } }
    else              { src = Wrh + (j0 + g - 12);               stride = 512; }

    // weights resident in registers for the whole scan
    float w[32];
#pragma unroll
    for (int k = 0; k < 32; k++) w[k] = 0.f;
    if (active) {
#pragma unroll
        for (int k = 0; k < 32; k++) w[k] = __ldg(src + (size_t)(l + 16 * k) * stride);
    }
    for (int i = tid; i < 400; i += NTHR) s_memW[i] = 0.f;

    for (int t = 0; t < n; t++) {
        const float* pxr = g_px + (size_t)t * NPAD;
        // -------- Phase A --------
        for (int i = tid; i < 512; i += NTHR)
            sh[i] = (t == 0) ? 0.f : __ldcg(&g_hbuf[i]);
        if (t > 0) {
            float gwp = s_gwprev;
            for (int i = tid; i < 400; i += NTHR) {
                int cc = i / 100;
                int row = i - cc * 100;
                float a = s_awprev[row];
                s_memW[i] = gwp * a * s_cw[cc] + (1.f - a) * s_memW[i];
            }
        }
        __syncthreads();
        if (g < 12 && active) {
            float acc = 0.f;
#pragma unroll
            for (int k = 0; k < 32; k++) acc += w[k] * sh[l + 16 * k];
            acc += __shfl_down_sync(0xffffffffu, acc, 8, 16);
            acc += __shfl_down_sync(0xffffffffu, acc, 4, 16);
            acc += __shfl_down_sync(0xffffffffu, acc, 2, 16);
            acc += __shfl_down_sync(0xffffffffu, acc, 1, 16);
            if (l == 0) s_u[g] = acc;
        }
        __syncthreads();
        if (tid < 4) {
            float c = __ldg(&pxr[j0 + tid]) + s_u[tid];
            g_cbuf[j0 + tid] = fmaxf(c, 0.f);
        }
        if (b < 100) {
            if (tid == 4) g_uwp[b] = s_u[8];
            if (tid == 5) g_urp[b] = s_u[9];
        }
        if (b == 0) {
            if (tid == 6) g_gates[0] = 1.f / (1.f + expf(-(__ldg(&pxr[1224]) + s_u[10])));
            if (tid == 7) g_gates[1] = 1.f / (1.f + expf(-(__ldg(&pxr[1225]) + s_u[11])));
        }
        grid_barrier();
        // -------- Phase B --------
        for (int i = tid; i < 512; i += NTHR) sc[i] = __ldcg(&g_cbuf[i]);
        int wid = tid >> 5;
        if (wid == 0) {
            warp_softmax(g_urp, pxr + 1124, s_ar);
        } else if (wid == 1) {
            warp_softmax(g_uwp, pxr + 1024, s_awprev);
            if ((tid & 31) == 0) {
                s_gwprev = __ldcg(&g_gates[0]);
                s_go     = __ldcg(&g_gates[1]);
            }
        }
        __syncthreads();
        if (g >= 12) {
            float acc = 0.f;
#pragma unroll
            for (int k = 0; k < 32; k++) acc += w[k] * sc[l + 16 * k];
            acc += __shfl_down_sync(0xffffffffu, acc, 8, 16);
            acc += __shfl_down_sync(0xffffffffu, acc, 4, 16);
            acc += __shfl_down_sync(0xffffffffu, acc, 2, 16);
            acc += __shfl_down_sync(0xffffffffu, acc, 1, 16);
            if (l == 0) s_cw[g - 12] = acc;
        }
        if (g < 4) {
            float acc = 0.f;
            for (int row = l; row < 100; row += 16)
                acc += s_ar[row] * s_memW[g * 100 + row];
            acc += __shfl_down_sync(0xffffffffu, acc, 8, 16);
            acc += __shfl_down_sync(0xffffffffu, acc, 4, 16);
            acc += __shfl_down_sync(0xffffffffu, acc, 2, 16);
            acc += __shfl_down_sync(0xffffffffu, acc, 1, 16);
            if (l == 0) {
                float hn = __ldg(&pxr[512 + j0 + g]) + s_u[4 + g] + s_go * acc;
                hn = fmaxf(hn, 0.f);
                out[(size_t)t * 512 + j0 + g] = hn;
                g_hbuf[j0 + g] = hn;
            }
        }
        grid_barrier();
    }
}

// ---------------- launch --------------------------------------------------------
extern "C" void kernel_launch(void* const* d_in, const int* in_sizes, int n_in,
                              void* d_out, int out_size) {
    const float* X   = (const float*)d_in[0];
    const float* Wc  = (const float*)d_in[1];
    const float* bc  = (const float*)d_in[2];
    const float* Wwg = (const float*)d_in[3];
    const float* bwg = (const float*)d_in[4];
    const float* Wwp = (const float*)d_in[5];
    const float* bwp = (const float*)d_in[6];
    const float* Wrg = (const float*)d_in[7];
    const float* brg = (const float*)d_in[8];
    const float* Wrp = (const float*)d_in[9];
    const float* brp = (const float*)d_in[10];
    const float* Wxh = (const float*)d_in[11];
    const float* Wrh = (const float*)d_in[12];
    const float* Whh = (const float*)d_in[13];
    const float* bh  = (const float*)d_in[14];
    float* out = (float*)d_out;

    int n = in_sizes[0] / 1024;
    if (n > MAXT) n = MAXT;

    init_kernel<<<1, 1>>>();
    pack_kernel<<<256, 256>>>(Wc, Wxh, Wwp, Wrp, Wwg, Wrg, bc, bh, bwp, brp, bwg, brg);
    dim3 gg((n + 63) / 64, NPAD / 64);
    gemm_kernel<<<gg, 256>>>(X, n);
    serial_kernel<<<NB, NTHR>>>(Wc, Wwp, Wrp, Wwg, Wrg, Whh, Wrh, out, n);
}

// round 13
// speedup vs baseline: 1.0564x; 1.0493x over previous
#include <cuda_runtime.h>
#include <math.h>

#define NPAD 1280
#define MAXT 32768
#define NB   128
#define NTHR 256

// ---------------- device scratch (static: allocation at module load, allowed) ----
__device__ float g_px[(size_t)MAXT * NPAD];   // precomputed x-projections (+bias)
__device__ float g_wpack[1024 * NPAD];        // packed x-part weights
__device__ float g_bias[NPAD];
__device__ float g_hbuf[512];
__device__ float g_cbuf[512];
__device__ float g_uwp[128];
__device__ float g_urp[128];
__device__ float g_gates[2];                  // [0]=gw, [1]=go
__device__ unsigned g_bar_count;
__device__ volatile unsigned g_bar_gen;

// ---------------- init (reset barrier state every launch / graph replay) --------
__global__ void init_kernel() {
    g_bar_count = 0u;
    g_bar_gen = 0u;
}

// ---------------- pack x-part weights + biases into one matrix ------------------
// columns: [0,512) Wc_x | [512,1024) Wxh | [1024,1124) Wwp_x | [1124,1224) Wrp_x
//          | 1224 wwg_x | 1225 wrg_x | rest 0
__global__ void pack_kernel(const float* __restrict__ Wc, const float* __restrict__ Wxh,
                            const float* __restrict__ Wwp, const float* __restrict__ Wrp,
                            const float* __restrict__ Wwg, const float* __restrict__ Wrg,
                            const float* __restrict__ bc, const float* __restrict__ bh,
                            const float* __restrict__ bwp, const float* __restrict__ brp,
                            const float* __restrict__ bwg, const float* __restrict__ brg) {
    int stride = gridDim.x * blockDim.x;
    int tid0 = blockIdx.x * blockDim.x + threadIdx.x;
    for (int idx = tid0; idx < 1024 * NPAD; idx += stride) {
        int row = idx / NPAD;
        int col = idx - row * NPAD;
        float v = 0.f;
        if (col < 512)        v = Wc[row * 512 + col];
        else if (col < 1024)  v = Wxh[row * 512 + (col - 512)];
        else if (col < 1124)  v = Wwp[row * 100 + (col - 1024)];
        else if (col < 1224)  v = Wrp[row * 100 + (col - 1124)];
        else if (col == 1224) v = Wwg[row];
        else if (col == 1225) v = Wrg[row];
        g_wpack[idx] = v;
    }
    if (tid0 < NPAD) {
        int t = tid0;
        float b = 0.f;
        if (t < 512)        b = bc[t];
        else if (t < 1024)  b = bh[t - 512];
        else if (t < 1124)  b = bwp[t - 1024];
        else if (t < 1224)  b = brp[t - 1124];
        else if (t == 1224) b = bwg[0];
        else if (t == 1225) b = brg[0];
        g_bias[t] = b;
    }
}

// ---------------- fp32 tiled GEMM: g_px[n,1280] = X[n,1024] @ g_wpack + bias -----
__global__ void __launch_bounds__(256) gemm_kernel(const float* __restrict__ X, int n) {
    __shared__ float As[16][64];       // [k][m]
    __shared__ float Bs[16][64];       // [k][n]
    const int tid = threadIdx.x;
    const int tx = tid & 15;           // N micro
    const int ty = tid >> 4;           // M micro
    const int m0 = blockIdx.x * 64;
    const int n0 = blockIdx.y * 64;

    const int am = tid >> 2;           // row 0..63 within A tile
    const int ak = (tid & 3) * 4;      // k offset 0..12
    const int bk = tid >> 4;           // k row 0..15
    const int bn = (tid & 15) * 4;     // n offset

    float acc[4][4];
#pragma unroll
    for (int i = 0; i < 4; i++)
#pragma unroll
        for (int j = 0; j < 4; j++) acc[i][j] = 0.f;

    for (int kt = 0; kt < 1024; kt += 16) {
        float4 xa;
        if (m0 + am < n)
            xa = *reinterpret_cast<const float4*>(X + (size_t)(m0 + am) * 1024 + kt + ak);
        else
            xa = make_float4(0.f, 0.f, 0.f, 0.f);
        As[ak + 0][am] = xa.x;
        As[ak + 1][am] = xa.y;
        As[ak + 2][am] = xa.z;
        As[ak + 3][am] = xa.w;
        float4 wb = *reinterpret_cast<const float4*>(g_wpack + (size_t)(kt + bk) * NPAD + n0 + bn);
        Bs[bk][bn + 0] = wb.x;
        Bs[bk][bn + 1] = wb.y;
        Bs[bk][bn + 2] = wb.z;
        Bs[bk][bn + 3] = wb.w;
        __syncthreads();
#pragma unroll
        for (int k = 0; k < 16; k++) {
            float4 av = *reinterpret_cast<const float4*>(&As[k][ty * 4]);
            float4 bv = *reinterpret_cast<const float4*>(&Bs[k][tx * 4]);
            float a[4] = {av.x, av.y, av.z, av.w};
            float b[4] = {bv.x, bv.y, bv.z, bv.w};
#pragma unroll
            for (int i = 0; i < 4; i++)
#pragma unroll
                for (int j = 0; j < 4; j++) acc[i][j] += a[i] * b[j];
        }
        __syncthreads();
    }
#pragma unroll
    for (int i = 0; i < 4; i++) {
        int r = m0 + ty * 4 + i;
        if (r >= n) continue;
#pragma unroll
        for (int j = 0; j < 4; j++) {
            int c = n0 + tx * 4 + j;
            g_px[(size_t)r * NPAD + c] = acc[i][j] + g_bias[c];
        }
    }
}

// ---------------- global barrier (all NB CTAs co-resident: NB <= 148) -----------
__device__ __forceinline__ void grid_barrier() {
    __syncthreads();
    if (threadIdx.x == 0) {
        __threadfence();                       // release my CTA's writes (gpu scope)
        unsigned gen = g_bar_gen;
        unsigned rank = atomicAdd(&g_bar_count, 1u);
        if (rank == NB - 1u) {
            atomicExch(&g_bar_count, 0u);
            __threadfence();
            g_bar_gen = gen + 1u;
        } else {
            while (g_bar_gen == gen) { }
        }
        __threadfence();                       // acquire
    }
    __syncthreads();
}

// warp-wide softmax over 100 elements: dst[m] = softmax(ubuf[m] + pxp[m])
__device__ __forceinline__ void warp_softmax(const float* ubuf, const float* __restrict__ pxp,
                                             float* dst) {
    int lane = threadIdx.x & 31;
    float v[4];
#pragma unroll
    for (int q = 0; q < 4; q++) {
        int m = lane + 32 * q;
        v[q] = (m < 100) ? (__ldcg(&ubuf[m]) + __ldg(&pxp[m])) : -1e30f;
    }
    float mx = fmaxf(fmaxf(v[0], v[1]), fmaxf(v[2], v[3]));
#pragma unroll
    for (int off = 16; off > 0; off >>= 1)
        mx = fmaxf(mx, __shfl_xor_sync(0xffffffffu, mx, off));
    float e[4], s = 0.f;
#pragma unroll
    for (int q = 0; q < 4; q++) {
        int m = lane + 32 * q;
        e[q] = (m < 100) ? expf(v[q] - mx) : 0.f;
        s += e[q];
    }
#pragma unroll
    for (int off = 16; off > 0; off >>= 1)
        s += __shfl_xor_sync(0xffffffffu, s, off);
    float inv = 1.f / s;
#pragma unroll
    for (int q = 0; q < 4; q++) {
        int m = lane + 32 * q;
        if (m < 100) dst[m] = e[q] * inv;
    }
}

// ---------------- persistent serial scan kernel ---------------------------------
// CTA b owns output columns j0=4b..4b+3 of Wc_h/Whh/Wrh and memW, plus (b<100)
// column b of Wwp_h/Wrp_h; CTA 0 owns the two gate dots.
// Group g = tid/16 (16 lanes each):
//   g 0..3  : u_c  = h . Wc_h[:,j0+g]
//   g 4..7  : u_hh = h . Whh[:,j0+g-4]
//   g 8     : u_wp = h . Wwp_h[:,b]            (b<100)
//   g 9     : u_rp = h . Wrp_h[:,b]            (b<100)
//   g 10,11 : gate dots (b==0)
//   g 12..15: cW   = c . Wrh[:,j0+g-12]        (phase B)
__global__ void __launch_bounds__(NTHR) serial_kernel(
    const float* __restrict__ Wc, const float* __restrict__ Wwp, const float* __restrict__ Wrp,
    const float* __restrict__ Wwg, const float* __restrict__ Wrg,
    const float* __restrict__ Whh, const float* __restrict__ Wrh,
    float* __restrict__ out, int n) {
    const int b = blockIdx.x;
    const int tid = threadIdx.x;
    const int g = tid >> 4;
    const int l = tid & 15;
    const int j0 = b * 4;

    __shared__ float sh[512];
    __shared__ float sc[512];
    __shared__ float s_ar[100];
    __shared__ float s_awprev[100];
    __shared__ float s_u[16];
    __shared__ float s_cw[4];
    __shared__ float s_go, s_gwprev;
    __shared__ float s_memW[400];     // [cc*100 + row]

    // select this thread's dot column source
    const float* src = Wc;            // dummy
    int stride = 512;
    bool active = true;
    if (g < 4)        { src = Wc  + 1024 * 512 + (j0 + g);       stride = 512; }
    else if (g < 8)   { src = Whh + (j0 + g - 4);                stride = 512; }
    else if (g == 8)  { active = (b < 100); if (active) { src = Wwp + 1024 * 100 + b; stride = 100; } }
    else if (g == 9)  { active = (b < 100); if (active) { src = Wrp + 1024 * 100 + b; stride = 100; } }
    else if (g == 10) { active = (b == 0);  if (active) { src = Wwg + 1024; stride = 1; } }
    else if (g == 11) { active = (b == 0);  if (active) { src = Wrg + 1024; stride = 1; } }
    else              { src = Wrh + (j0 + g - 12);               stride = 512; }

    // weights resident in registers for the whole scan
    float w[32];
#pragma unroll
    for (int k = 0; k < 32; k++) w[k] = 0.f;
    if (active) {
#pragma unroll
        for (int k = 0; k < 32; k++) w[k] = __ldg(src + (size_t)(l + 16 * k) * stride);
    }
    for (int i = tid; i < 400; i += NTHR) s_memW[i] = 0.f;

    for (int t = 0; t < n; t++) {
        const float* pxr = g_px + (size_t)t * NPAD;
        // -------- Phase A --------
        for (int i = tid; i < 512; i += NTHR)
            sh[i] = (t == 0) ? 0.f : __ldcg(&g_hbuf[i]);
        if (t > 0) {
            float gwp = s_gwprev;
            for (int i = tid; i < 400; i += NTHR) {
                int cc = i / 100;
                int row = i - cc * 100;
                float a = s_awprev[row];
                s_memW[i] = gwp * a * s_cw[cc] + (1.f - a) * s_memW[i];
            }
        }
        __syncthreads();
        if (g < 12 && active) {
            float acc = 0.f;
#pragma unroll
            for (int k = 0; k < 32; k++) acc += w[k] * sh[l + 16 * k];
            acc += __shfl_down_sync(0xffffffffu, acc, 8, 16);
            acc += __shfl_down_sync(0xffffffffu, acc, 4, 16);
            acc += __shfl_down_sync(0xffffffffu, acc, 2, 16);
            acc += __shfl_down_sync(0xffffffffu, acc, 1, 16);
            if (l == 0) s_u[g] = acc;
        }
        __syncthreads();
        if (tid < 4) {
            float c = __ldg(&pxr[j0 + tid]) + s_u[tid];
            g_cbuf[j0 + tid] = fmaxf(c, 0.f);
        }
        if (b < 100) {
            if (tid == 4) g_uwp[b] = s_u[8];
            if (tid == 5) g_urp[b] = s_u[9];
        }
        if (b == 0) {
            if (tid == 6) g_gates[0] = 1.f / (1.f + expf(-(__ldg(&pxr[1224]) + s_u[10])));
            if (tid == 7) g_gates[1] = 1.f / (1.f + expf(-(__ldg(&pxr[1225]) + s_u[11])));
        }
        grid_barrier();
        // -------- Phase B --------
        for (int i = tid; i < 512; i += NTHR) sc[i] = __ldcg(&g_cbuf[i]);
        int wid = tid >> 5;
        if (wid == 0) {
            warp_softmax(g_urp, pxr + 1124, s_ar);
        } else if (wid == 1) {
            warp_softmax(g_uwp, pxr + 1024, s_awprev);
            if ((tid & 31) == 0) {
                s_gwprev = __ldcg(&g_gates[0]);
                s_go     = __ldcg(&g_gates[1]);
            }
        }
        __syncthreads();
        if (g >= 12) {
            float acc = 0.f;
#pragma unroll
            for (int k = 0; k < 32; k++) acc += w[k] * sc[l + 16 * k];
            acc += __shfl_down_sync(0xffffffffu, acc, 8, 16);
            acc += __shfl_down_sync(0xffffffffu, acc, 4, 16);
            acc += __shfl_down_sync(0xffffffffu, acc, 2, 16);
            acc += __shfl_down_sync(0xffffffffu, acc, 1, 16);
            if (l == 0) s_cw[g - 12] = acc;
        }
        if (g < 4) {
            float acc = 0.f;
            for (int row = l; row < 100; row += 16)
                acc += s_ar[row] * s_memW[g * 100 + row];
            acc += __shfl_down_sync(0xffffffffu, acc, 8, 16);
            acc += __shfl_down_sync(0xffffffffu, acc, 4, 16);
            acc += __shfl_down_sync(0xffffffffu, acc, 2, 16);
            acc += __shfl_down_sync(0xffffffffu, acc, 1, 16);
            if (l == 0) {
                float hn = __ldg(&pxr[512 + j0 + g]) + s_u[4 + g] + s_go * acc;
                hn = fmaxf(hn, 0.f);
                out[(size_t)t * 512 + j0 + g] = hn;
                g_hbuf[j0 + g] = hn;
            }
        }
        grid_barrier();
    }
}

// ---------------- launch --------------------------------------------------------
extern "C" void kernel_launch(void* const* d_in, const int* in_sizes, int n_in,
                              void* d_out, int out_size) {
    const float* X   = (const float*)d_in[0];
    const float* Wc  = (const float*)d_in[1];
    const float* bc  = (const float*)d_in[2];
    const float* Wwg = (const float*)d_in[3];
    const float* bwg = (const float*)d_in[4];
    const float* Wwp = (const float*)d_in[5];
    const float* bwp = (const float*)d_in[6];
    const float* Wrg = (const float*)d_in[7];
    const float* brg = (const float*)d_in[8];
    const float* Wrp = (const float*)d_in[9];
    const float* brp = (const float*)d_in[10];
    const float* Wxh = (const float*)d_in[11];
    const float* Wrh = (const float*)d_in[12];
    const float* Whh = (const float*)d_in[13];
    const float* bh  = (const float*)d_in[14];
    float* out = (float*)d_out;

    int n = in_sizes[0] / 1024;
    if (n > MAXT) n = MAXT;

    init_kernel<<<1, 1>>>();
    pack_kernel<<<256, 256>>>(Wc, Wxh, Wwp, Wrp, Wwg, Wrg, bc, bh, bwp, brp, bwg, brg);
    dim3 gg((n + 63) / 64, NPAD / 64);
    gemm_kernel<<<gg, 256>>>(X, n);
    serial_kernel<<<NB, NTHR>>>(Wc, Wwp, Wrp, Wwg, Wrg, Whh, Wrh, out, n);
}